// round 2
// baseline (speedup 1.0000x reference)
#include <cuda_runtime.h>
#include <cstdint>

#define NUM_RADIAL    16
#define NUM_SPHERICAL 8
#define CUTOFF        6.0f
#define MAX_EDGES     400000

// Precomputed radial basis table [E, 16] — 25.6 MB, L2-resident during gather.
// 16B-aligned: accessed via float4.
__device__ __align__(16) float g_rbf[MAX_EDGES * NUM_RADIAL];

// ---------------------------------------------------------------------------
// Kernel 1: rbf[e, r] = env(d) * norm/D * sin((r+1)*pi*d_scaled)
// ---------------------------------------------------------------------------
__global__ void rbf_kernel(const float* __restrict__ D_ca, int E) {
    int e = blockIdx.x * blockDim.x + threadIdx.x;
    if (e >= E) return;

    float D = D_ca[e];
    float ds = D * (1.0f / CUTOFF);

    // polynomial envelope, p = 5: 1 - 21 d^5 + 35 d^6 - 15 d^7
    float d2 = ds * ds;
    float d4 = d2 * d2;
    float d5 = d4 * ds;
    float env = 1.0f + d5 * (-21.0f + ds * (35.0f + ds * (-15.0f)));
    if (ds >= 1.0f) env = 0.0f;

    // norm = sqrt(2 / CUTOFF^3) = sqrt(1/108)
    const float norm = 0.09622504486493764f;
    float pref = env * norm / D;

    const float PI = 3.14159265358979323846f;
    float base = PI * ds;

    float4 out[4];
    float* o = (float*)out;
#pragma unroll
    for (int r = 0; r < NUM_RADIAL; r++) {
        o[r] = pref * sinf((float)(r + 1) * base);
    }
    float4* dst = (float4*)(g_rbf + (size_t)e * NUM_RADIAL);
    dst[0] = out[0]; dst[1] = out[1]; dst[2] = out[2]; dst[3] = out[3];
}

// ---------------------------------------------------------------------------
// Kernel 2: one warp per triplet.
// Lane l produces out[t, 4l .. 4l+3]:  s = l>>2, r = (l&3)*4 .. +3
//   out[t, s*16 + r] = cbf_s(cos_phi[t]) * rbf[id3[t], r]
// NOTE: id3 is int32 on device (JAX x64 disabled downcasts int64 -> int32).
// ---------------------------------------------------------------------------
__global__ void triplet_kernel(const float* __restrict__ cos_phi,
                               const int* __restrict__ id3,
                               float* __restrict__ out,
                               int T) {
    unsigned gtid = blockIdx.x * blockDim.x + threadIdx.x;
    unsigned t = gtid >> 5;
    if (t >= (unsigned)T) return;
    unsigned lane = gtid & 31;

    float c  = __ldg(cos_phi + t);
    int   id = __ldg(id3 + t);

    // gaussian smearing: centers linspace(-1,1,8), delta = 2/7,
    // coeff = -0.5/delta^2 = -6.125
    int   s    = lane >> 2;
    float off  = -1.0f + (2.0f / 7.0f) * (float)s;
    float diff = c - off;
    float cb   = __expf(-6.125f * diff * diff);

    // lane's 4 radial values: float4 (l&3) of row id
    const float4* row = (const float4*)(g_rbf + (size_t)id * NUM_RADIAL);
    float4 rv = __ldg(row + (lane & 3));

    float4 res;
    res.x = cb * rv.x;
    res.y = cb * rv.y;
    res.z = cb * rv.z;
    res.w = cb * rv.w;

    // row t is 512 B; lane l writes float4 #l -> one coalesced wavefront set
    float4* dst = (float4*)out + (size_t)t * 32 + lane;
    *dst = res;
}

extern "C" void kernel_launch(void* const* d_in, const int* in_sizes, int n_in,
                              void* d_out, int out_size) {
    const float* D_ca    = (const float*)d_in[0];
    const float* cos_phi = (const float*)d_in[1];
    const int*   id3     = (const int*)d_in[2];
    float*       out     = (float*)d_out;

    int E = in_sizes[0];
    int T = in_sizes[1];

    // Kernel 1: build rbf table
    {
        int threads = 256;
        int blocks = (E + threads - 1) / threads;
        rbf_kernel<<<blocks, threads>>>(D_ca, E);
    }

    // Kernel 2: one warp per triplet
    {
        int threads = 256;                       // 8 warps / block
        long long total_threads = (long long)T * 32;
        int blocks = (int)((total_threads + threads - 1) / threads);
        triplet_kernel<<<blocks, threads>>>(cos_phi, id3, out, T);
    }
}

// round 4
// speedup vs baseline: 1.6283x; 1.6283x over previous
#include <cuda_runtime.h>
#include <cstdint>

#define NUM_RADIAL    16
#define NUM_SPHERICAL 8
#define CUTOFF        6.0f
#define MAX_EDGES     400000

// Precomputed radial basis table [E, 16] — 25.6 MB, L2-resident during gather.
__device__ __align__(16) float g_rbf[MAX_EDGES * NUM_RADIAL];

// ---------------------------------------------------------------------------
// Kernel 1: rbf[e, r] = env(d) * norm/D * sin((r+1)*pi*d_scaled)
// ---------------------------------------------------------------------------
__global__ void rbf_kernel(const float* __restrict__ D_ca, int E) {
    int e = blockIdx.x * blockDim.x + threadIdx.x;
    if (e >= E) return;

    float D = D_ca[e];
    float ds = D * (1.0f / CUTOFF);

    // polynomial envelope, p = 5: 1 - 21 d^5 + 35 d^6 - 15 d^7
    float d2 = ds * ds;
    float d4 = d2 * d2;
    float d5 = d4 * ds;
    float env = 1.0f + d5 * (-21.0f + ds * (35.0f + ds * (-15.0f)));
    if (ds >= 1.0f) env = 0.0f;

    const float norm = 0.09622504486493764f;   // sqrt(2/6^3)
    float pref = env * norm / D;

    const float PI = 3.14159265358979323846f;
    float base = PI * ds;

    float4 out[4];
    float* o = (float*)out;
#pragma unroll
    for (int r = 0; r < NUM_RADIAL; r++) {
        o[r] = pref * sinf((float)(r + 1) * base);
    }
    float4* dst = (float4*)(g_rbf + (size_t)e * NUM_RADIAL);
    dst[0] = out[0]; dst[1] = out[1]; dst[2] = out[2]; dst[3] = out[3];
}

// ---------------------------------------------------------------------------
// Kernel 2: one warp per 32 triplets.
//  - lane l loads cos_phi[base+l], id3[base+l]  (coalesced)
//  - loop over the 32 triplets in groups of 8 (shfl broadcast):
//      * issue 8 independent rbf gathers (MLP=8)
//      * compute gaussian, multiply, store 8 x 512B coalesced rows
//  Output row t: lane l writes float4 #l  (s = l>>2, r = (l&3)*4..+3).
// ---------------------------------------------------------------------------
__global__ void __launch_bounds__(256) triplet_kernel(
        const float* __restrict__ cos_phi,
        const int* __restrict__ id3,
        float* __restrict__ out,
        int T) {
    int warp = (blockIdx.x * blockDim.x + threadIdx.x) >> 5;
    int lane = threadIdx.x & 31;
    int base = warp << 5;                    // 32 triplets per warp
    if (base >= T) return;

    bool full = (base + 32) <= T;
    int  my_t = base + lane;

    float c_all  = 0.0f;
    int   id_all = 0;
    if (full || my_t < T) {
        c_all  = __ldg(cos_phi + my_t);
        id_all = __ldg(id3 + my_t);
    }

    // lane-fixed constants
    float off   = -1.0f + (2.0f / 7.0f) * (float)(lane >> 2);
    int   rquad = lane & 3;
    float4* outv = (float4*)out;

    if (full) {
#pragma unroll
        for (int g = 0; g < 32; g += 8) {
            float4 rv[8];
            float  cj[8];
#pragma unroll
            for (int j = 0; j < 8; j++) {
                int   idj = __shfl_sync(0xffffffffu, id_all, g + j);
                cj[j]     = __shfl_sync(0xffffffffu, c_all, g + j);
                rv[j] = __ldg((const float4*)(g_rbf + (size_t)idj * NUM_RADIAL)
                              + rquad);
            }
#pragma unroll
            for (int j = 0; j < 8; j++) {
                float d  = cj[j] - off;
                float cb = __expf(-6.125f * d * d);
                float4 r;
                r.x = cb * rv[j].x;
                r.y = cb * rv[j].y;
                r.z = cb * rv[j].z;
                r.w = cb * rv[j].w;
                outv[(size_t)(base + g + j) * 32 + lane] = r;
            }
        }
    } else {
        int nt = T - base;
        for (int j = 0; j < nt; j++) {
            int   idj = __shfl_sync(0xffffffffu, id_all, j);
            float c   = __shfl_sync(0xffffffffu, c_all, j);
            float4 rv = __ldg((const float4*)(g_rbf + (size_t)idj * NUM_RADIAL)
                              + rquad);
            float d  = c - off;
            float cb = __expf(-6.125f * d * d);
            float4 r;
            r.x = cb * rv.x; r.y = cb * rv.y; r.z = cb * rv.z; r.w = cb * rv.w;
            outv[(size_t)(base + j) * 32 + lane] = r;
        }
    }
}

extern "C" void kernel_launch(void* const* d_in, const int* in_sizes, int n_in,
                              void* d_out, int out_size) {
    const float* D_ca    = (const float*)d_in[0];
    const float* cos_phi = (const float*)d_in[1];
    const int*   id3     = (const int*)d_in[2];
    float*       out     = (float*)d_out;

    int E = in_sizes[0];
    int T = in_sizes[1];

    {
        int threads = 256;
        int blocks = (E + threads - 1) / threads;
        rbf_kernel<<<blocks, threads>>>(D_ca, E);
    }
    {
        int threads = 256;                          // 8 warps/block
        int warps_needed = (T + 31) / 32;           // 32 triplets per warp
        int blocks = (warps_needed + 7) / 8;
        triplet_kernel<<<blocks, threads>>>(cos_phi, id3, out, T);
    }
}

// round 9
// speedup vs baseline: 1.8000x; 1.1055x over previous
#include <cuda_runtime.h>
#include <cstdint>

#define NUM_RADIAL    16
#define NUM_SPHERICAL 8
#define CUTOFF        6.0f
#define MAX_EDGES     400000

// Precomputed radial basis table [E, 16] — 25.6 MB, L2-resident during gather.
__device__ __align__(16) float g_rbf[MAX_EDGES * NUM_RADIAL];

__device__ __forceinline__ void cp_async16(uint32_t dst_smem, const void* src) {
    asm volatile("cp.async.cg.shared.global [%0], [%1], 16;"
                 :: "r"(dst_smem), "l"(src));
}

// ---------------------------------------------------------------------------
// Kernel 1: rbf[e, r] = env(d) * norm/D * sin((r+1)*pi*d_scaled)
// One sincosf + Chebyshev recurrence instead of 16 sinf calls.
// ---------------------------------------------------------------------------
__global__ void rbf_kernel(const float* __restrict__ D_ca, int E) {
    int e = blockIdx.x * blockDim.x + threadIdx.x;
    if (e >= E) return;

    float D = D_ca[e];
    float ds = D * (1.0f / CUTOFF);

    // polynomial envelope, p = 5: 1 - 21 d^5 + 35 d^6 - 15 d^7
    float d2 = ds * ds;
    float d4 = d2 * d2;
    float d5 = d4 * ds;
    float env = 1.0f + d5 * (-21.0f + ds * (35.0f + ds * (-15.0f)));
    if (ds >= 1.0f) env = 0.0f;

    const float norm = 0.09622504486493764f;   // sqrt(2/6^3)
    float pref = env * norm / D;

    const float PI = 3.14159265358979323846f;
    float x = PI * ds;

    float s1, c1;
    sincosf(x, &s1, &c1);

    float4 outr[4];
    float* o = (float*)outr;
    float sn = s1, cn = c1;
    o[0] = pref * sn;
#pragma unroll
    for (int r = 1; r < NUM_RADIAL; r++) {
        float sn1 = fmaf(sn, c1, cn * s1);
        float cn1 = fmaf(cn, c1, -sn * s1);
        sn = sn1; cn = cn1;
        o[r] = pref * sn;
    }
    float4* dst = (float4*)(g_rbf + (size_t)e * NUM_RADIAL);
    dst[0] = outr[0]; dst[1] = outr[1]; dst[2] = outr[2]; dst[3] = outr[3];
}

// ---------------------------------------------------------------------------
// Kernel 2: one warp per 32 triplets.
//  - lane l loads cos_phi[base+l], id3[base+l]  (coalesced)
//  - 4x cp.async.cg: warp fetches all 32 gathered rbf rows (2 KB) into smem
//    (32 in-flight 16B requests, zero register cost)
//  - consume: 32 iterations, smem broadcast read + expf + coalesced
//    512B STG.128 row with evict-first hint (protect L2-resident rbf table)
// ---------------------------------------------------------------------------
__global__ void __launch_bounds__(256) triplet_kernel(
        const float* __restrict__ cos_phi,
        const int* __restrict__ id3,
        float* __restrict__ out,
        int T) {
    __shared__ float4 sm[8][32][4];          // 16 KB: 8 warps x 32 rows x 64 B

    int wib  = threadIdx.x >> 5;
    int lane = threadIdx.x & 31;
    int warp = (blockIdx.x * blockDim.x + threadIdx.x) >> 5;
    int base = warp << 5;
    if (base >= T) return;

    bool full = (base + 32) <= T;
    int  my_t = base + lane;

    float c_all  = 0.0f;
    int   id_all = 0;
    if (full || my_t < T) {
        c_all  = __ldg(cos_phi + my_t);
        id_all = __ldg(id3 + my_t);
    }

    float off   = -1.0f + (2.0f / 7.0f) * (float)(lane >> 2);
    int   rquad = lane & 3;
    float4* outv = (float4*)out;

    if (full) {
        // Fetch all 32 rows: lane l handles row (g*8 + l>>2), quad (l&3).
        int subrow = lane >> 2;
#pragma unroll
        for (int g = 0; g < 4; g++) {
            int j   = g * 8 + subrow;
            int idj = __shfl_sync(0xffffffffu, id_all, j);
            const float4* src = (const float4*)(g_rbf + (size_t)idj * NUM_RADIAL)
                                + rquad;
            uint32_t dst = (uint32_t)__cvta_generic_to_shared(&sm[wib][j][rquad]);
            cp_async16(dst, src);
        }
        asm volatile("cp.async.commit_group;");
        asm volatile("cp.async.wait_group 0;" ::: "memory");
        __syncwarp();

#pragma unroll 8
        for (int j = 0; j < 32; j++) {
            float  c  = __shfl_sync(0xffffffffu, c_all, j);
            float4 rv = sm[wib][j][rquad];
            float  d  = c - off;
            float  cb = __expf(-6.125f * d * d);
            float4 r;
            r.x = cb * rv.x; r.y = cb * rv.y; r.z = cb * rv.z; r.w = cb * rv.w;
            __stcs(outv + (size_t)(base + j) * 32 + lane, r);
        }
    } else {
        int nt = T - base;
        for (int j = 0; j < nt; j++) {
            int   idj = __shfl_sync(0xffffffffu, id_all, j);
            float c   = __shfl_sync(0xffffffffu, c_all, j);
            float4 rv = __ldg((const float4*)(g_rbf + (size_t)idj * NUM_RADIAL)
                              + rquad);
            float d  = c - off;
            float cb = __expf(-6.125f * d * d);
            float4 r;
            r.x = cb * rv.x; r.y = cb * rv.y; r.z = cb * rv.z; r.w = cb * rv.w;
            __stcs(outv + (size_t)(base + j) * 32 + lane, r);
        }
    }
}

extern "C" void kernel_launch(void* const* d_in, const int* in_sizes, int n_in,
                              void* d_out, int out_size) {
    const float* D_ca    = (const float*)d_in[0];
    const float* cos_phi = (const float*)d_in[1];
    const int*   id3     = (const int*)d_in[2];
    float*       out     = (float*)d_out;

    int E = in_sizes[0];
    int T = in_sizes[1];

    {
        int threads = 256;
        int blocks = (E + threads - 1) / threads;
        rbf_kernel<<<blocks, threads>>>(D_ca, E);
    }
    {
        int threads = 256;                          // 8 warps/block
        int warps_needed = (T + 31) / 32;           // 32 triplets per warp
        int blocks = (warps_needed + 7) / 8;
        triplet_kernel<<<blocks, threads>>>(cos_phi, id3, out, T);
    }
}